// round 14
// baseline (speedup 1.0000x reference)
#include <cuda_runtime.h>
#include <math.h>
#include <stdint.h>

#define B_  2
#define T_  2048
#define C_  1024
#define H_  16
#define HD_ 64
#define N1_ 6
#define N2_ 4
#define M_  (B_*T_)   // 4096

// ---------------- scratch (no allocation allowed) ----------------
__device__ float g_q[(size_t)B_ * H_ * T_ * HD_];
__device__ float g_k[(size_t)B_ * H_ * T_ * HD_];
__device__ float g_v[(size_t)B_ * H_ * T_ * HD_];   // TRANSPOSED: [bh][d][t]
__device__ float g_tq[(size_t)B_ * H_ * T_];
__device__ float g_tk[(size_t)B_ * H_ * T_];
__device__ float g_y[(size_t)M_ * C_];
__device__ float g_xt[(size_t)M_ * C_];
__device__ float g_wq[(size_t)3 * C_ * C_];
__device__ float g_wp[(size_t)C_ * C_];
__device__ float2 g_rot[(size_t)T_ * 32];           // {cos,sin} table

// ---------------- tf32 helpers ----------------
__device__ __forceinline__ uint32_t f2tf32(float f) {
    uint32_t u;
    asm("cvt.rna.tf32.f32 %0, %1;" : "=r"(u) : "f"(f));
    return u;
}
__device__ __forceinline__ void mma_tf32(float& c0, float& c1, float& c2, float& c3,
                                         uint32_t a0, uint32_t a1, uint32_t a2, uint32_t a3,
                                         uint32_t b0, uint32_t b1) {
    asm volatile(
        "mma.sync.aligned.m16n8k8.row.col.f32.tf32.tf32.f32 "
        "{%0,%1,%2,%3}, {%4,%5,%6,%7}, {%8,%9}, {%0,%1,%2,%3};"
        : "+f"(c0), "+f"(c1), "+f"(c2), "+f"(c3)
        : "r"(a0), "r"(a1), "r"(a2), "r"(a3), "r"(b0), "r"(b1));
}
__device__ __forceinline__ uint32_t smem_u32(const void* p) {
    uint32_t a;
    asm("{ .reg .u64 tmp; cvta.to.shared.u64 tmp, %1; cvt.u32.u64 %0, tmp; }"
        : "=r"(a) : "l"(p));
    return a;
}
__device__ __forceinline__ void cp16(uint32_t dst, const void* src) {
    asm volatile("cp.async.cg.shared.global [%0], [%1], 16;"
                 :: "r"(dst), "l"(src) : "memory");
}
__device__ __forceinline__ void ldm4(uint32_t& r0, uint32_t& r1, uint32_t& r2, uint32_t& r3,
                                     uint32_t addr) {
    asm volatile("ldmatrix.sync.aligned.m8n8.x4.shared.b16 {%0,%1,%2,%3}, [%4];"
                 : "=r"(r0), "=r"(r1), "=r"(r2), "=r"(r3) : "r"(addr));
}

// ---------------- elementwise tf32 rounding pass ----------------
__global__ __launch_bounds__(256) void cvt_tf32_kernel(
    const float4* __restrict__ src, uint4* __restrict__ dst, int n4)
{
    int i = blockIdx.x * 256 + threadIdx.x;
    if (i < n4) {
        float4 f = src[i];
        uint4 u;
        u.x = f2tf32(f.x); u.y = f2tf32(f.y);
        u.z = f2tf32(f.z); u.w = f2tf32(f.w);
        dst[i] = u;
    }
}

// ---------------- rotary cos/sin table ----------------
__global__ __launch_bounds__(256) void rotab_kernel()
{
    const int t = blockIdx.x * 8 + (threadIdx.x >> 5);
    const int d = threadIdx.x & 31;
    const float LOG2_1E4 = 13.287712379549449f;
    float inv_freq = exp2f(-(float)d * (LOG2_1E4 / 32.0f));
    float sn, cs;
    sincosf((float)t * inv_freq, &sn, &cs);
    g_rot[(size_t)t * 32 + d] = make_float2(cs, sn);
}

// ================= tf32 mma.sync GEMM, 3-stage cp.async, ldmatrix frags ====
// EPI: 1 = bias + plain store; 2 = fused rotary/norm/tq-tk/V-transpose (qkv)
#define SPAD   36
#define GSTG   9216
#define GBOFF  4608
#define GSM_BYTES (3 * GSTG * 4)

template<int EPI>
__global__ __launch_bounds__(256, 2) void mma_gemm(
    const float* __restrict__ A, const float* __restrict__ Bm,
    const float* __restrict__ bias, float* __restrict__ Cm,
    int M, int N, int K, const float* __restrict__ curv)
{
    extern __shared__ float gsm[];
    const uint32_t sbase = smem_u32(gsm);

    const int tid = threadIdx.x;
    const int wid = tid >> 5, lane = tid & 31;
    const int g = lane >> 2, tig = lane & 3;
    const int warp_m = wid >> 2, warp_n = wid & 3;
    const int bm = blockIdx.y * 128, bn = blockIdx.x * 128;

    const int r  = tid >> 1;
    const int cq = (tid & 1) * 16;
    const float* Ap = A + (size_t)(bm + r) * K + cq;
    const float* Bp = Bm + (size_t)(bn + r) * K + cq;
    const uint32_t sA = sbase + (uint32_t)(r * SPAD + cq) * 4;
    const uint32_t sB = sA + GBOFF * 4;

    const int arow  = warp_m * 64 + (lane & 15);
    const int acol  = (lane >> 4) * 4;
    const int brow  = (lane & 7) + ((lane & 16) ? 8 : 0);
    const int bcol  = (lane & 8) ? 4 : 0;

    float acc[4][4][4];
    #pragma unroll
    for (int i = 0; i < 4; i++)
        #pragma unroll
        for (int j = 0; j < 4; j++)
            #pragma unroll
            for (int q = 0; q < 4; q++) acc[i][j][q] = 0.0f;

    const int nk = K >> 5;

    auto issue = [&](int c, int s) {
        const float* ag = Ap + c * 32;
        const float* bg = Bp + c * 32;
        const uint32_t off = (uint32_t)(s * GSTG) * 4;
        #pragma unroll
        for (int j = 0; j < 4; j++) {
            cp16(sA + off + j * 16, ag + 4 * j);
            cp16(sB + off + j * 16, bg + 4 * j);
        }
        asm volatile("cp.async.commit_group;" ::: "memory");
    };

    issue(0, 0);
    issue(1, 1);

    for (int i = 0; i < nk; i++) {
        if (i + 2 < nk) {
            asm volatile("cp.async.wait_group 1;" ::: "memory");
        } else {
            asm volatile("cp.async.wait_group 0;" ::: "memory");
        }
        __syncthreads();

        if (i + 2 < nk) issue(i + 2, (i + 2) % 3);

        const uint32_t sAs = sbase + (uint32_t)((i % 3) * GSTG) * 4;
        const uint32_t sBs = sAs + GBOFF * 4;
        const uint32_t aAddr0 = sAs + (uint32_t)(arow * SPAD + acol) * 4;
        const uint32_t bAddr0 = sBs + (uint32_t)((warp_n * 32 + brow) * SPAD + bcol) * 4;

        #pragma unroll
        for (int kk = 0; kk < 4; kk++) {
            const int k0 = kk * 8;
            uint32_t afr[4][4], bfr[4][2];
            #pragma unroll
            for (int mf = 0; mf < 4; mf++)
                ldm4(afr[mf][0], afr[mf][1], afr[mf][2], afr[mf][3],
                     aAddr0 + (uint32_t)(mf * 16 * SPAD + k0) * 4);
            #pragma unroll
            for (int p = 0; p < 2; p++)
                ldm4(bfr[2*p][0], bfr[2*p][1], bfr[2*p+1][0], bfr[2*p+1][1],
                     bAddr0 + (uint32_t)(p * 16 * SPAD + k0) * 4);
            #pragma unroll
            for (int mf = 0; mf < 4; mf++)
                #pragma unroll
                for (int nf = 0; nf < 4; nf++)
                    mma_tf32(acc[mf][nf][0], acc[mf][nf][1], acc[mf][nf][2], acc[mf][nf][3],
                             afr[mf][0], afr[mf][1], afr[mf][2], afr[mf][3],
                             bfr[nf][0], bfr[nf][1]);
        }
    }

    if (EPI == 1) {
        #pragma unroll
        for (int mf = 0; mf < 4; mf++) {
            const int row0 = bm + warp_m * 64 + mf * 16 + g;
            #pragma unroll
            for (int nf = 0; nf < 4; nf++) {
                const int col = bn + warp_n * 32 + nf * 8 + tig * 2;
                float b0 = bias[col], b1 = bias[col + 1];
                float2 v0, v1;
                v0.x = acc[mf][nf][0] + b0; v0.y = acc[mf][nf][1] + b1;
                v1.x = acc[mf][nf][2] + b0; v1.y = acc[mf][nf][3] + b1;
                *(float2*)(Cm + (size_t)row0 * N + col)       = v0;
                *(float2*)(Cm + (size_t)(row0 + 8) * N + col) = v1;
            }
        }
    } else {
        // ---- fused rotary / norm / tq-tk / V-transpose epilogue ----
        __syncthreads();                       // all smem stage reads done
        float* yt = gsm;                       // [128][132]
        #pragma unroll
        for (int mf = 0; mf < 4; mf++) {
            const int rl0 = warp_m * 64 + mf * 16 + g;
            #pragma unroll
            for (int nf = 0; nf < 4; nf++) {
                const int cl = warp_n * 32 + nf * 8 + tig * 2;
                *(float2*)&yt[rl0 * 132 + cl] =
                    make_float2(acc[mf][nf][0], acc[mf][nf][1]);
                *(float2*)&yt[(rl0 + 8) * 132 + cl] =
                    make_float2(acc[mf][nf][2], acc[mf][nf][3]);
            }
        }
        __syncthreads();

        const int region  = bn >> 10;          // 0=q, 1=k, 2=v
        const int colbase = bn & 1023;
        const int b  = bm >> 11;
        const int t0 = bm & 2047;

        if (region < 2) {
            const int rl = tid >> 1, hs = tid & 1;
            const int t = t0 + rl;
            const int h = (colbase >> 6) + hs;
            float* row = yt + rl * 132 + hs * 64;
            const float2* rot = g_rot + (size_t)t * 32;

            float sum = 0.f;
            #pragma unroll
            for (int d = 0; d < 32; d++) {
                float2 cssn = rot[d];
                float a  = row[d], b2 = row[d + 32];
                float ra = fmaf(a,  cssn.x,  b2 * cssn.y);
                float rb = fmaf(b2, cssn.x, -a  * cssn.y);
                row[d] = ra; row[d + 32] = rb;
                sum = fmaf(ra, ra, fmaf(rb, rb, sum));
            }

            float scale = 1.0f;
            if (h >= N1_ + N2_) {
                scale = 1.0f / fmaxf(sqrtf(sum), 1e-12f);
            } else if (h >= N1_) {
                float c = curv[h - N1_];
                float tv = sqrtf(1.0f / c + sum);
                if (region == 0) g_tq[(size_t)(b * H_ + h) * T_ + t] = tv;
                else             g_tk[(size_t)(b * H_ + h) * T_ + t] = tv;
            }

            float* dst = (region == 0 ? g_q : g_k)
                         + ((size_t)(b * H_ + h) * T_ + t) * HD_;
            #pragma unroll
            for (int j = 0; j < 16; j++) {
                uint4 u;
                u.x = f2tf32(row[4*j + 0] * scale);
                u.y = f2tf32(row[4*j + 1] * scale);
                u.z = f2tf32(row[4*j + 2] * scale);
                u.w = f2tf32(row[4*j + 3] * scale);
                ((uint4*)dst)[j] = u;
            }
        } else {
            // V: transpose-to-[bh][d][t] with tf32 rounding
            const int dl = tid & 127, tg = tid >> 7;
            const int h = (colbase >> 6) + (dl >> 6);
            const int d = dl & 63;
            float* dst = g_v + ((size_t)(b * H_ + h) * HD_ + d) * T_ + t0 + tg * 64;
            #pragma unroll
            for (int j = 0; j < 16; j++) {
                uint4 u;
                u.x = f2tf32(yt[(tg * 64 + 4*j + 0) * 132 + dl]);
                u.y = f2tf32(yt[(tg * 64 + 4*j + 1) * 132 + dl]);
                u.z = f2tf32(yt[(tg * 64 + 4*j + 2) * 132 + dl]);
                u.w = f2tf32(yt[(tg * 64 + 4*j + 3) * 132 + dl]);
                ((uint4*)dst)[j] = u;
            }
        }
    }
}

// ---------------- flash: 2 q-tiles (128 queries) per block, shared K/V ----------
#define FK_STG 17408
#define FV_OFF 34816
#define FV_STG 17408
#define FP_OFF 69632
#define FT_OFF 104448
#define FSM_BYTES 104960

__global__ __launch_bounds__(256, 2) void flash_tc(const float* __restrict__ curv)
{
    extern __shared__ char dsm[];
    const uint32_t sb = smem_u32(dsm);
    uint32_t (*Ps)[68] = (uint32_t(*)[68])(dsm + FP_OFF);

    const int bh = blockIdx.y;
    const int qtp = (int)gridDim.x - 1 - (int)blockIdx.x;
    const int h = bh % H_, b = bh / H_;
    const int mode = (h < N1_) ? 0 : (h < N1_ + N2_ ? 1 : 2);
    const int tid = threadIdx.x;
    const int lane = tid & 31;
    const int warp = tid >> 5;
    const int wh = warp >> 2;
    const int wq = warp & 3;
    const int qt_own = 2 * qtp + wh;
    const int qt_max = 2 * qtp + 1;
    const int g = lane >> 2, tig = lane & 3;
    const int r0 = wq * 16;
    const int prow_lo = wh * 64 + r0 + g, prow_hi = prow_lo + 8;
    const int rlo = r0 + g, rhi = rlo + 8;

    const int brow = (lane & 7) + ((lane & 16) ? 8 : 0);
    const int bcol = (lane & 8) ? 4 : 0;
    const int parow = wh * 64 + r0 + (lane & 15);
    const int pacol = (lane >> 4) * 4;

    const int klr = tid >> 2;
    const int kcq = (tid & 3) * 16;
    auto issue = [&](int c, int st) {
        if (c <= qt_max) {
            const float* ksrc = g_k + ((size_t)bh * T_ + c * 64 + klr) * HD_ + kcq;
            const float* vsrc = g_v + ((size_t)bh * HD_ + klr) * T_ + c * 64 + kcq;
            const uint32_t kdst = sb + st * FK_STG + klr * 272 + kcq * 4;
            const uint32_t vdst = sb + FV_OFF + st * FV_STG + klr * 272 + kcq * 4;
            #pragma unroll
            for (int j = 0; j < 4; j++) {
                cp16(kdst + j * 16, ksrc + j * 4);
                cp16(vdst + j * 16, vsrc + j * 4);
            }
            if (mode == 1 && tid < 16)
                cp16(sb + FT_OFF + st * 256 + tid * 16,
                     g_tk + (size_t)bh * T_ + c * 64 + tid * 4);
        }
        asm volatile("cp.async.commit_group;" ::: "memory");
    };

    issue(0, 0);

    {
        const int lr = tid >> 1, lc = (tid & 1) * 32;
        const uint4* src = (const uint4*)(g_q + ((size_t)bh * T_ + qtp * 128 + lr) * HD_ + lc);
        #pragma unroll
        for (int i = 0; i < 8; i++)
            *(uint4*)&Ps[lr][lc + 4*i] = src[i];
    }
    __syncthreads();
    uint32_t qf[8][4];
    #pragma unroll
    for (int k0 = 0; k0 < 8; k0++) {
        const int kb8 = k0 * 8;
        qf[k0][0] = Ps[prow_lo][kb8 + tig];
        qf[k0][1] = Ps[prow_hi][kb8 + tig];
        qf[k0][2] = Ps[prow_lo][kb8 + tig + 4];
        qf[k0][3] = Ps[prow_hi][kb8 + tig + 4];
    }
    __syncthreads();

    const float scl = (mode == 0) ? 0.125f : 8.0f;
    float cu = 1.f, rcinv = 1.f, ctq0 = 0.f, ctq1 = 0.f;
    if (mode == 1) {
        cu = curv[h - N1_];
        rcinv = rsqrtf(cu);
        ctq0 = cu * g_tq[(size_t)bh * T_ + qt_own * 64 + rlo];
        ctq1 = cu * g_tq[(size_t)bh * T_ + qt_own * 64 + rhi];
    }

    float m0 = -INFINITY, m1 = -INFINITY, l0 = 0.f, l1 = 0.f;
    float of[8][4];
    #pragma unroll
    for (int nf = 0; nf < 8; nf++)
        #pragma unroll
        for (int q = 0; q < 4; q++) of[nf][q] = 0.f;

    for (int kt = 0; kt <= qt_max; kt++) {
        const int st = kt & 1;
        issue(kt + 1, st ^ 1);
        if (kt + 1 <= qt_max) {
            asm volatile("cp.async.wait_group 1;" ::: "memory");
        } else {
            asm volatile("cp.async.wait_group 0;" ::: "memory");
        }
        __syncthreads();

        if (kt <= qt_own) {
            const uint32_t kbase = sb + st * FK_STG + (uint32_t)(brow * 68 + bcol) * 4;
            const uint32_t vbase = sb + FV_OFF + st * FV_STG + (uint32_t)(brow * 68 + bcol) * 4;
            const uint32_t pbase = sb + FP_OFF + (uint32_t)(parow * 68 + pacol) * 4;
            const float* tks = (const float*)(dsm + FT_OFF + st * 256);

            float sf[8][4];
            #pragma unroll
            for (int nf = 0; nf < 8; nf++)
                #pragma unroll
                for (int q = 0; q < 4; q++) sf[nf][q] = 0.f;
            #pragma unroll
            for (int k0 = 0; k0 < 8; k0++) {
                const int kb8 = k0 * 8;
                #pragma unroll
                for (int p = 0; p < 4; p++) {
                    uint32_t b00, b01, b10, b11;
                    ldm4(b00, b01, b10, b11,
                         kbase + (uint32_t)(p * 16 * 68 + kb8) * 4);
                    mma_tf32(sf[2*p][0], sf[2*p][1], sf[2*p][2], sf[2*p][3],
                             qf[k0][0], qf[k0][1], qf[k0][2], qf[k0][3], b00, b01);
                    mma_tf32(sf[2*p+1][0], sf[2*p+1][1], sf[2*p+1][2], sf[2*p+1][3],
                             qf[k0][0], qf[k0][1], qf[k0][2], qf[k0][3], b10, b11);
                }
            }

            if (mode != 1) {
                #pragma unroll
                for (int nf = 0; nf < 8; nf++) {
                    sf[nf][0] *= scl; sf[nf][1] *= scl;
                    sf[nf][2] *= scl; sf[nf][3] *= scl;
                }
            } else {
                #pragma unroll
                for (int nf = 0; nf < 8; nf++) {
                    const int cc = nf * 8 + 2 * tig;
                    const float tk0 = tks[cc], tk1 = tks[cc + 1];
                    #pragma unroll
                    for (int q = 0; q < 4; q++) {
                        const float tkv = (q & 1) ? tk1 : tk0;
                        const float ctq = (q & 2) ? ctq1 : ctq0;
                        float am1 = fmaf(-cu, sf[nf][q], fmaf(ctq, tkv, -1.0f));
                        am1 = fmaxf(am1, 1e-7f);
                        float x = am1 * (am1 + 2.0f);
                        float root = x * rsqrtf(x);
                        float dis = rcinv * __logf(am1 + 1.0f + root);
                        sf[nf][q] = __fdividef(1.0f, 1e-6f + dis);
                    }
                }
            }

            if (kt == qt_own) {
                #pragma unroll
                for (int nf = 0; nf < 8; nf++) {
                    const int cc = nf * 8 + 2 * tig;
                    if (cc     > rlo) sf[nf][0] = -1e30f;
                    if (cc + 1 > rlo) sf[nf][1] = -1e30f;
                    if (cc     > rhi) sf[nf][2] = -1e30f;
                    if (cc + 1 > rhi) sf[nf][3] = -1e30f;
                }
            }

            float mx0 = -INFINITY, mx1 = -INFINITY;
            #pragma unroll
            for (int nf = 0; nf < 8; nf++) {
                mx0 = fmaxf(mx0, fmaxf(sf[nf][0], sf[nf][1]));
                mx1 = fmaxf(mx1, fmaxf(sf[nf][2], sf[nf][3]));
            }
            mx0 = fmaxf(mx0, __shfl_xor_sync(0xffffffffu, mx0, 1));
            mx0 = fmaxf(mx0, __shfl_xor_sync(0xffffffffu, mx0, 2));
            mx1 = fmaxf(mx1, __shfl_xor_sync(0xffffffffu, mx1, 1));
            mx1 = fmaxf(mx1, __shfl_xor_sync(0xffffffffu, mx1, 2));
            const float mn0 = fmaxf(m0, mx0), mn1 = fmaxf(m1, mx1);
            const float cr0 = __expf(m0 - mn0), cr1 = __expf(m1 - mn1);

            float s0 = 0.f, s1 = 0.f;
            #pragma unroll
            for (int nf = 0; nf < 8; nf++) {
                float p0 = __expf(sf[nf][0] - mn0);
                float p1 = __expf(sf[nf][1] - mn0);
                float p2 = __expf(sf[nf][2] - mn1);
                float p3 = __expf(sf[nf][3] - mn1);
                s0 += p0 + p1; s1 += p2 + p3;
                const int cc = nf * 8 + 2 * tig;
                Ps[prow_lo][cc]     = f2tf32(p0);
                Ps[prow_lo][cc + 1] = f2tf32(p1);
                Ps[prow_hi][cc]     = f2tf32(p2);
                Ps[prow_hi][cc + 1] = f2tf32(p3);
                of[nf][0] *= cr0; of[nf][1] *= cr0;
                of[nf][2] *= cr1; of[nf][3] *= cr1;
            }
            s0 += __shfl_xor_sync(0xffffffffu, s0, 1);
            s0 += __shfl_xor_sync(0xffffffffu, s0, 2);
            s1 += __shfl_xor_sync(0xffffffffu, s1, 1);
            s1 += __shfl_xor_sync(0xffffffffu, s1, 2);
            l0 = l0 * cr0 + s0;
            l1 = l1 * cr1 + s1;
            m0 = mn0; m1 = mn1;
            __syncwarp();

            #pragma unroll
            for (int k0 = 0; k0 < 8; k0++) {
                const int kb8 = k0 * 8;
                uint32_t a0, a1, a2, a3;
                ldm4(a0, a1, a2, a3, pbase + (uint32_t)kb8 * 4);
                #pragma unroll
                for (int p = 0; p < 4; p++) {
                    uint32_t b00, b01, b10, b11;
                    ldm4(b00, b01, b10, b11,
                         vbase + (uint32_t)(p * 16 * 68 + kb8) * 4);
                    mma_tf32(of[2*p][0], of[2*p][1], of[2*p][2], of[2*p][3],
                             a0, a1, a2, a3, b00, b01);
                    mma_tf32(of[2*p+1][0], of[2*p+1][1], of[2*p+1][2], of[2*p+1][3],
                             a0, a1, a2, a3, b10, b11);
                }
            }
        }
        __syncthreads();
    }

    const float il0 = 1.0f / l0, il1 = 1.0f / l1;
    const int rowg_lo = b * T_ + qt_own * 64 + rlo;
    const int rowg_hi = rowg_lo + 8;
    #pragma unroll
    for (int nf = 0; nf < 8; nf++) {
        const int col = h * HD_ + nf * 8 + 2 * tig;
        uint2 vlo, vhi;
        vlo.x = f2tf32(of[nf][0] * il0); vlo.y = f2tf32(of[nf][1] * il0);
        vhi.x = f2tf32(of[nf][2] * il1); vhi.y = f2tf32(of[nf][3] * il1);
        *(uint2*)(g_y + (size_t)rowg_lo * C_ + col) = vlo;
        *(uint2*)(g_y + (size_t)rowg_hi * C_ + col) = vhi;
    }
}

// ---------------- launch ----------------
extern "C" void kernel_launch(void* const* d_in, const int* in_sizes, int n_in,
                              void* d_out, int out_size)
{
    const float* x      = (const float*)d_in[0];
    const float* qkv_w  = (const float*)d_in[1];
    const float* proj_w = (const float*)d_in[2];
    const float* proj_b = (const float*)d_in[3];
    const float* curv   = (const float*)d_in[4];
    float* out = (float*)d_out;

    void *py = nullptr, *pxt = nullptr, *pwq = nullptr, *pwp = nullptr;
    cudaGetSymbolAddress(&py, g_y);
    cudaGetSymbolAddress(&pxt, g_xt);
    cudaGetSymbolAddress(&pwq, g_wq);
    cudaGetSymbolAddress(&pwp, g_wp);

    cudaFuncSetAttribute(flash_tc,
                         cudaFuncAttributeMaxDynamicSharedMemorySize, FSM_BYTES);
    cudaFuncSetAttribute(mma_gemm<1>,
                         cudaFuncAttributeMaxDynamicSharedMemorySize, GSM_BYTES);
    cudaFuncSetAttribute(mma_gemm<2>,
                         cudaFuncAttributeMaxDynamicSharedMemorySize, GSM_BYTES);

    // 0) tf32-round GEMM inputs + rotary table
    cvt_tf32_kernel<<<(M_ * C_ / 4 + 255) / 256, 256>>>(
        (const float4*)x, (uint4*)pxt, M_ * C_ / 4);
    cvt_tf32_kernel<<<(3 * C_ * C_ / 4 + 255) / 256, 256>>>(
        (const float4*)qkv_w, (uint4*)pwq, 3 * C_ * C_ / 4);
    cvt_tf32_kernel<<<(C_ * C_ / 4 + 255) / 256, 256>>>(
        (const float4*)proj_w, (uint4*)pwp, C_ * C_ / 4);
    rotab_kernel<<<T_ / 8, 256>>>();

    // 1) qkv GEMM with fused rotary/norm/tq-tk/V-transpose epilogue
    mma_gemm<2><<<dim3(3 * C_ / 128, M_ / 128), 256, GSM_BYTES>>>(
        (const float*)pxt, (const float*)pwq, nullptr, nullptr, M_, 3 * C_, C_, curv);

    // 2) flash: 2 q-tiles per block, shared K/V
    flash_tc<<<dim3(T_ / 128, B_ * H_), 256, FSM_BYTES>>>(curv);

    // 3) out = y @ proj_w^T + proj_b
    mma_gemm<1><<<dim3(C_ / 128, M_ / 128), 256, GSM_BYTES>>>(
        (const float*)py, (const float*)pwp, proj_b, out, M_, C_, C_, nullptr);
}

// round 15
// speedup vs baseline: 1.4179x; 1.4179x over previous
#include <cuda_runtime.h>
#include <cuda_fp16.h>
#include <math.h>
#include <stdint.h>

#define B_  2
#define T_  2048
#define C_  1024
#define H_  16
#define HD_ 64
#define N1_ 6
#define N2_ 4
#define M_  (B_*T_)   // 4096

// ---------------- scratch (no allocation allowed) ----------------
__device__ float g_q[(size_t)B_ * H_ * T_ * HD_];
__device__ float g_k[(size_t)B_ * H_ * T_ * HD_];
__device__ float g_v[(size_t)B_ * H_ * T_ * HD_];   // TRANSPOSED: [bh][d][t]
__device__ float g_tq[(size_t)B_ * H_ * T_];
__device__ float g_tk[(size_t)B_ * H_ * T_];
__device__ __half g_yh[(size_t)M_ * C_];            // attn out, fp16
__device__ __half g_xh[(size_t)M_ * C_];            // fp16 x
__device__ __half g_wqh[(size_t)3 * C_ * C_];       // fp16 qkv_w
__device__ __half g_wph[(size_t)C_ * C_];           // fp16 proj_w
__device__ float2 g_rot[(size_t)T_ * 32];           // {cos,sin} table

// ---------------- helpers ----------------
__device__ __forceinline__ uint32_t f2tf32(float f) {
    uint32_t u;
    asm("cvt.rna.tf32.f32 %0, %1;" : "=r"(u) : "f"(f));
    return u;
}
__device__ __forceinline__ void mma_tf32(float& c0, float& c1, float& c2, float& c3,
                                         uint32_t a0, uint32_t a1, uint32_t a2, uint32_t a3,
                                         uint32_t b0, uint32_t b1) {
    asm volatile(
        "mma.sync.aligned.m16n8k8.row.col.f32.tf32.tf32.f32 "
        "{%0,%1,%2,%3}, {%4,%5,%6,%7}, {%8,%9}, {%0,%1,%2,%3};"
        : "+f"(c0), "+f"(c1), "+f"(c2), "+f"(c3)
        : "r"(a0), "r"(a1), "r"(a2), "r"(a3), "r"(b0), "r"(b1));
}
__device__ __forceinline__ void mma_f16(float& c0, float& c1, float& c2, float& c3,
                                        uint32_t a0, uint32_t a1, uint32_t a2, uint32_t a3,
                                        uint32_t b0, uint32_t b1) {
    asm volatile(
        "mma.sync.aligned.m16n8k16.row.col.f32.f16.f16.f32 "
        "{%0,%1,%2,%3}, {%4,%5,%6,%7}, {%8,%9}, {%0,%1,%2,%3};"
        : "+f"(c0), "+f"(c1), "+f"(c2), "+f"(c3)
        : "r"(a0), "r"(a1), "r"(a2), "r"(a3), "r"(b0), "r"(b1));
}
__device__ __forceinline__ uint32_t smem_u32(const void* p) {
    uint32_t a;
    asm("{ .reg .u64 tmp; cvta.to.shared.u64 tmp, %1; cvt.u32.u64 %0, tmp; }"
        : "=r"(a) : "l"(p));
    return a;
}
__device__ __forceinline__ void cp16(uint32_t dst, const void* src) {
    asm volatile("cp.async.cg.shared.global [%0], [%1], 16;"
                 :: "r"(dst), "l"(src) : "memory");
}
__device__ __forceinline__ void ldm4(uint32_t& r0, uint32_t& r1, uint32_t& r2, uint32_t& r3,
                                     uint32_t addr) {
    asm volatile("ldmatrix.sync.aligned.m8n8.x4.shared.b16 {%0,%1,%2,%3}, [%4];"
                 : "=r"(r0), "=r"(r1), "=r"(r2), "=r"(r3) : "r"(addr));
}

// ---------------- fp32 -> fp16 conversion pass ----------------
__global__ __launch_bounds__(256) void cvt_f16_kernel(
    const float4* __restrict__ src, __half2* __restrict__ dst, int n4)
{
    int i = blockIdx.x * 256 + threadIdx.x;
    if (i < n4) {
        float4 f = src[i];
        dst[2 * i]     = __floats2half2_rn(f.x, f.y);
        dst[2 * i + 1] = __floats2half2_rn(f.z, f.w);
    }
}

// ---------------- rotary cos/sin table ----------------
__global__ __launch_bounds__(256) void rotab_kernel()
{
    const int t = blockIdx.x * 8 + (threadIdx.x >> 5);
    const int d = threadIdx.x & 31;
    const float LOG2_1E4 = 13.287712379549449f;
    float inv_freq = exp2f(-(float)d * (LOG2_1E4 / 32.0f));
    float sn, cs;
    sincosf((float)t * inv_freq, &sn, &cs);
    g_rot[(size_t)t * 32 + d] = make_float2(cs, sn);
}

// ================= fp16 mma.sync GEMM, 3-stage cp.async, ldmatrix frags ====
// A [M,K], B [N,K] fp16; C = A B^T, fp32 accum.
// EPI: 1 = bias + fp32 store; 2 = fused rotary/norm/tq-tk/V-transpose (qkv)
#define SPADH  40                      // halves per row (80 B, conflict-free)
#define HSTG_B 20480                   // bytes per stage (A 10240 + B 10240)
#define HBOFF  10240
#define GSM_BYTES 67584                // max(3*HSTG_B, yt 128*132*4)

template<int EPI>
__global__ __launch_bounds__(256, 2) void mma_gemm(
    const __half* __restrict__ A, const __half* __restrict__ Bm,
    const float* __restrict__ bias, float* __restrict__ Cm,
    int M, int N, int K, const float* __restrict__ curv)
{
    extern __shared__ float gsm[];
    const uint32_t sbase = smem_u32(gsm);

    const int tid = threadIdx.x;
    const int wid = tid >> 5, lane = tid & 31;
    const int g = lane >> 2, tig = lane & 3;
    const int warp_m = wid >> 2, warp_n = wid & 3;
    const int bm = blockIdx.y * 128, bn = blockIdx.x * 128;

    const int r  = tid >> 1;
    const int cq = (tid & 1) * 16;     // half column base
    const __half* Ap = A + (size_t)(bm + r) * K + cq;
    const __half* Bp = Bm + (size_t)(bn + r) * K + cq;
    const uint32_t sA = sbase + (uint32_t)(r * SPADH + cq) * 2;
    const uint32_t sB = sA + HBOFF;

    // ldmatrix lane coords (halves)
    const int arow = warp_m * 64 + (lane & 15);           // + mf*16
    const int acol = (lane >> 4) * 8;                     // + k0
    const int brow = (lane & 7) + ((lane & 16) ? 8 : 0);  // + warp_n*32 + p*16
    const int bcol = (lane & 8) ? 8 : 0;                  // + k0

    float acc[4][4][4];
    #pragma unroll
    for (int i = 0; i < 4; i++)
        #pragma unroll
        for (int j = 0; j < 4; j++)
            #pragma unroll
            for (int q = 0; q < 4; q++) acc[i][j][q] = 0.0f;

    const int nk = K >> 5;             // 32-half chunks

    auto issue = [&](int c, int s) {
        const __half* ag = Ap + c * 32;
        const __half* bg = Bp + c * 32;
        const uint32_t off = (uint32_t)(s * HSTG_B);
        #pragma unroll
        for (int j = 0; j < 2; j++) {
            cp16(sA + off + j * 16, ag + 8 * j);
            cp16(sB + off + j * 16, bg + 8 * j);
        }
        asm volatile("cp.async.commit_group;" ::: "memory");
    };

    issue(0, 0);
    issue(1, 1);

    for (int i = 0; i < nk; i++) {
        if (i + 2 < nk) {
            asm volatile("cp.async.wait_group 1;" ::: "memory");
        } else {
            asm volatile("cp.async.wait_group 0;" ::: "memory");
        }
        __syncthreads();

        if (i + 2 < nk) issue(i + 2, (i + 2) % 3);

        const uint32_t sAs = sbase + (uint32_t)((i % 3) * HSTG_B);
        const uint32_t sBs = sAs + HBOFF;
        const uint32_t aAddr0 = sAs + (uint32_t)(arow * SPADH + acol) * 2;
        const uint32_t bAddr0 = sBs + (uint32_t)((warp_n * 32 + brow) * SPADH + bcol) * 2;

        #pragma unroll
        for (int kk = 0; kk < 2; kk++) {
            const int k0 = kk * 16;    // halves
            uint32_t afr[4][4], bfr[4][2];
            #pragma unroll
            for (int mf = 0; mf < 4; mf++)
                ldm4(afr[mf][0], afr[mf][1], afr[mf][2], afr[mf][3],
                     aAddr0 + (uint32_t)(mf * 16 * SPADH + k0) * 2);
            #pragma unroll
            for (int p = 0; p < 2; p++)
                ldm4(bfr[2*p][0], bfr[2*p][1], bfr[2*p+1][0], bfr[2*p+1][1],
                     bAddr0 + (uint32_t)(p * 16 * SPADH + k0) * 2);
            #pragma unroll
            for (int mf = 0; mf < 4; mf++)
                #pragma unroll
                for (int nf = 0; nf < 4; nf++)
                    mma_f16(acc[mf][nf][0], acc[mf][nf][1], acc[mf][nf][2], acc[mf][nf][3],
                            afr[mf][0], afr[mf][1], afr[mf][2], afr[mf][3],
                            bfr[nf][0], bfr[nf][1]);
        }
    }

    if (EPI == 1) {
        #pragma unroll
        for (int mf = 0; mf < 4; mf++) {
            const int row0 = bm + warp_m * 64 + mf * 16 + g;
            #pragma unroll
            for (int nf = 0; nf < 4; nf++) {
                const int col = bn + warp_n * 32 + nf * 8 + tig * 2;
                float b0 = bias[col], b1 = bias[col + 1];
                float2 v0, v1;
                v0.x = acc[mf][nf][0] + b0; v0.y = acc[mf][nf][1] + b1;
                v1.x = acc[mf][nf][2] + b0; v1.y = acc[mf][nf][3] + b1;
                *(float2*)(Cm + (size_t)row0 * N + col)       = v0;
                *(float2*)(Cm + (size_t)(row0 + 8) * N + col) = v1;
            }
        }
    } else {
        // ---- fused rotary / norm / tq-tk / V-transpose epilogue ----
        __syncthreads();
        float* yt = gsm;               // [128][132]
        #pragma unroll
        for (int mf = 0; mf < 4; mf++) {
            const int rl0 = warp_m * 64 + mf * 16 + g;
            #pragma unroll
            for (int nf = 0; nf < 4; nf++) {
                const int cl = warp_n * 32 + nf * 8 + tig * 2;
                *(float2*)&yt[rl0 * 132 + cl] =
                    make_float2(acc[mf][nf][0], acc[mf][nf][1]);
                *(float2*)&yt[(rl0 + 8) * 132 + cl] =
                    make_float2(acc[mf][nf][2], acc[mf][nf][3]);
            }
        }
        __syncthreads();

        const int region  = bn >> 10;  // 0=q, 1=k, 2=v
        const int colbase = bn & 1023;
        const int b  = bm >> 11;
        const int t0 = bm & 2047;

        if (region < 2) {
            const int rl = tid >> 1, hs = tid & 1;
            const int t = t0 + rl;
            const int h = (colbase >> 6) + hs;
            float* row = yt + rl * 132 + hs * 64;
            const float2* rot = g_rot + (size_t)t * 32;

            float sum = 0.f;
            #pragma unroll
            for (int d = 0; d < 32; d++) {
                float2 cssn = rot[d];
                float a  = row[d], b2 = row[d + 32];
                float ra = fmaf(a,  cssn.x,  b2 * cssn.y);
                float rb = fmaf(b2, cssn.x, -a  * cssn.y);
                row[d] = ra; row[d + 32] = rb;
                sum = fmaf(ra, ra, fmaf(rb, rb, sum));
            }

            float scale = 1.0f;
            if (h >= N1_ + N2_) {
                scale = 1.0f / fmaxf(sqrtf(sum), 1e-12f);
            } else if (h >= N1_) {
                float c = curv[h - N1_];
                float tv = sqrtf(1.0f / c + sum);
                if (region == 0) g_tq[(size_t)(b * H_ + h) * T_ + t] = tv;
                else             g_tk[(size_t)(b * H_ + h) * T_ + t] = tv;
            }

            float* dst = (region == 0 ? g_q : g_k)
                         + ((size_t)(b * H_ + h) * T_ + t) * HD_;
            #pragma unroll
            for (int j = 0; j < 16; j++) {
                uint4 u;
                u.x = f2tf32(row[4*j + 0] * scale);
                u.y = f2tf32(row[4*j + 1] * scale);
                u.z = f2tf32(row[4*j + 2] * scale);
                u.w = f2tf32(row[4*j + 3] * scale);
                ((uint4*)dst)[j] = u;
            }
        } else {
            const int dl = tid & 127, tg = tid >> 7;
            const int h = (colbase >> 6) + (dl >> 6);
            const int d = dl & 63;
            float* dst = g_v + ((size_t)(b * H_ + h) * HD_ + d) * T_ + t0 + tg * 64;
            #pragma unroll
            for (int j = 0; j < 16; j++) {
                uint4 u;
                u.x = f2tf32(yt[(tg * 64 + 4*j + 0) * 132 + dl]);
                u.y = f2tf32(yt[(tg * 64 + 4*j + 1) * 132 + dl]);
                u.z = f2tf32(yt[(tg * 64 + 4*j + 2) * 132 + dl]);
                u.w = f2tf32(yt[(tg * 64 + 4*j + 3) * 132 + dl]);
                ((uint4*)dst)[j] = u;
            }
        }
    }
}

// ---------------- flash: 2 q-tiles (128 queries) per block, shared K/V ----------
#define FK_STG 17408
#define FV_OFF 34816
#define FV_STG 17408
#define FP_OFF 69632
#define FT_OFF 104448
#define FSM_BYTES 104960

__global__ __launch_bounds__(256, 2) void flash_tc(const float* __restrict__ curv)
{
    extern __shared__ char dsm[];
    const uint32_t sb = smem_u32(dsm);
    uint32_t (*Ps)[68] = (uint32_t(*)[68])(dsm + FP_OFF);

    const int bh = blockIdx.y;
    const int qtp = (int)gridDim.x - 1 - (int)blockIdx.x;
    const int h = bh % H_, b = bh / H_;
    const int mode = (h < N1_) ? 0 : (h < N1_ + N2_ ? 1 : 2);
    const int tid = threadIdx.x;
    const int lane = tid & 31;
    const int warp = tid >> 5;
    const int wh = warp >> 2;
    const int wq = warp & 3;
    const int qt_own = 2 * qtp + wh;
    const int qt_max = 2 * qtp + 1;
    const int g = lane >> 2, tig = lane & 3;
    const int r0 = wq * 16;
    const int prow_lo = wh * 64 + r0 + g, prow_hi = prow_lo + 8;
    const int rlo = r0 + g, rhi = rlo + 8;

    const int brow = (lane & 7) + ((lane & 16) ? 8 : 0);
    const int bcol = (lane & 8) ? 4 : 0;
    const int parow = wh * 64 + r0 + (lane & 15);
    const int pacol = (lane >> 4) * 4;

    const int klr = tid >> 2;
    const int kcq = (tid & 3) * 16;
    auto issue = [&](int c, int st) {
        if (c <= qt_max) {
            const float* ksrc = g_k + ((size_t)bh * T_ + c * 64 + klr) * HD_ + kcq;
            const float* vsrc = g_v + ((size_t)bh * HD_ + klr) * T_ + c * 64 + kcq;
            const uint32_t kdst = sb + st * FK_STG + klr * 272 + kcq * 4;
            const uint32_t vdst = sb + FV_OFF + st * FV_STG + klr * 272 + kcq * 4;
            #pragma unroll
            for (int j = 0; j < 4; j++) {
                cp16(kdst + j * 16, ksrc + j * 4);
                cp16(vdst + j * 16, vsrc + j * 4);
            }
            if (mode == 1 && tid < 16)
                cp16(sb + FT_OFF + st * 256 + tid * 16,
                     g_tk + (size_t)bh * T_ + c * 64 + tid * 4);
        }
        asm volatile("cp.async.commit_group;" ::: "memory");
    };

    issue(0, 0);

    {
        const int lr = tid >> 1, lc = (tid & 1) * 32;
        const uint4* src = (const uint4*)(g_q + ((size_t)bh * T_ + qtp * 128 + lr) * HD_ + lc);
        #pragma unroll
        for (int i = 0; i < 8; i++)
            *(uint4*)&Ps[lr][lc + 4*i] = src[i];
    }
    __syncthreads();
    uint32_t qf[8][4];
    #pragma unroll
    for (int k0 = 0; k0 < 8; k0++) {
        const int kb8 = k0 * 8;
        qf[k0][0] = Ps[prow_lo][kb8 + tig];
        qf[k0][1] = Ps[prow_hi][kb8 + tig];
        qf[k0][2] = Ps[prow_lo][kb8 + tig + 4];
        qf[k0][3] = Ps[prow_hi][kb8 + tig + 4];
    }
    __syncthreads();

    const float scl = (mode == 0) ? 0.125f : 8.0f;
    float cu = 1.f, rcinv = 1.f, ctq0 = 0.f, ctq1 = 0.f;
    if (mode == 1) {
        cu = curv[h - N1_];
        rcinv = rsqrtf(cu);
        ctq0 = cu * g_tq[(size_t)bh * T_ + qt_own * 64 + rlo];
        ctq1 = cu * g_tq[(size_t)bh * T_ + qt_own * 64 + rhi];
    }

    float m0 = -INFINITY, m1 = -INFINITY, l0 = 0.f, l1 = 0.f;
    float of[8][4];
    #pragma unroll
    for (int nf = 0; nf < 8; nf++)
        #pragma unroll
        for (int q = 0; q < 4; q++) of[nf][q] = 0.f;

    for (int kt = 0; kt <= qt_max; kt++) {
        const int st = kt & 1;
        issue(kt + 1, st ^ 1);
        if (kt + 1 <= qt_max) {
            asm volatile("cp.async.wait_group 1;" ::: "memory");
        } else {
            asm volatile("cp.async.wait_group 0;" ::: "memory");
        }
        __syncthreads();

        if (kt <= qt_own) {
            const uint32_t kbase = sb + st * FK_STG + (uint32_t)(brow * 68 + bcol) * 4;
            const uint32_t vbase = sb + FV_OFF + st * FV_STG + (uint32_t)(brow * 68 + bcol) * 4;
            const uint32_t pbase = sb + FP_OFF + (uint32_t)(parow * 68 + pacol) * 4;
            const float* tks = (const float*)(dsm + FT_OFF + st * 256);

            float sf[8][4];
            #pragma unroll
            for (int nf = 0; nf < 8; nf++)
                #pragma unroll
                for (int q = 0; q < 4; q++) sf[nf][q] = 0.f;
            #pragma unroll
            for (int k0 = 0; k0 < 8; k0++) {
                const int kb8 = k0 * 8;
                #pragma unroll
                for (int p = 0; p < 4; p++) {
                    uint32_t b00, b01, b10, b11;
                    ldm4(b00, b01, b10, b11,
                         kbase + (uint32_t)(p * 16 * 68 + kb8) * 4);
                    mma_tf32(sf[2*p][0], sf[2*p][1], sf[2*p][2], sf[2*p][3],
                             qf[k0][0], qf[k0][1], qf[k0][2], qf[k0][3], b00, b01);
                    mma_tf32(sf[2*p+1][0], sf[2*p+1][1], sf[2*p+1][2], sf[2*p+1][3],
                             qf[k0][0], qf[k0][1], qf[k0][2], qf[k0][3], b10, b11);
                }
            }

            if (mode != 1) {
                #pragma unroll
                for (int nf = 0; nf < 8; nf++) {
                    sf[nf][0] *= scl; sf[nf][1] *= scl;
                    sf[nf][2] *= scl; sf[nf][3] *= scl;
                }
            } else {
                #pragma unroll
                for (int nf = 0; nf < 8; nf++) {
                    const int cc = nf * 8 + 2 * tig;
                    const float tk0 = tks[cc], tk1 = tks[cc + 1];
                    #pragma unroll
                    for (int q = 0; q < 4; q++) {
                        const float tkv = (q & 1) ? tk1 : tk0;
                        const float ctq = (q & 2) ? ctq1 : ctq0;
                        float am1 = fmaf(-cu, sf[nf][q], fmaf(ctq, tkv, -1.0f));
                        am1 = fmaxf(am1, 1e-7f);
                        float x = am1 * (am1 + 2.0f);
                        float root = x * rsqrtf(x);
                        float dis = rcinv * __logf(am1 + 1.0f + root);
                        sf[nf][q] = __fdividef(1.0f, 1e-6f + dis);
                    }
                }
            }

            if (kt == qt_own) {
                #pragma unroll
                for (int nf = 0; nf < 8; nf++) {
                    const int cc = nf * 8 + 2 * tig;
                    if (cc     > rlo) sf[nf][0] = -1e30f;
                    if (cc + 1 > rlo) sf[nf][1] = -1e30f;
                    if (cc     > rhi) sf[nf][2] = -1e30f;
                    if (cc + 1 > rhi) sf[nf][3] = -1e30f;
                }
            }

            float mx0 = -INFINITY, mx1 = -INFINITY;
            #pragma unroll
            for (int nf = 0; nf < 8; nf++) {
                mx0 = fmaxf(mx0, fmaxf(sf[nf][0], sf[nf][1]));
                mx1 = fmaxf(mx1, fmaxf(sf[nf][2], sf[nf][3]));
            }
            mx0 = fmaxf(mx0, __shfl_xor_sync(0xffffffffu, mx0, 1));
            mx0 = fmaxf(mx0, __shfl_xor_sync(0xffffffffu, mx0, 2));
            mx1 = fmaxf(mx1, __shfl_xor_sync(0xffffffffu, mx1, 1));
            mx1 = fmaxf(mx1, __shfl_xor_sync(0xffffffffu, mx1, 2));
            const float mn0 = fmaxf(m0, mx0), mn1 = fmaxf(m1, mx1);
            const float cr0 = __expf(m0 - mn0), cr1 = __expf(m1 - mn1);

            float s0 = 0.f, s1 = 0.f;
            #pragma unroll
            for (int nf = 0; nf < 8; nf++) {
                float p0 = __expf(sf[nf][0] - mn0);
                float p1 = __expf(sf[nf][1] - mn0);
                float p2 = __expf(sf[nf][2] - mn1);
                float p3 = __expf(sf[nf][3] - mn1);
                s0 += p0 + p1; s1 += p2 + p3;
                const int cc = nf * 8 + 2 * tig;
                Ps[prow_lo][cc]     = f2tf32(p0);
                Ps[prow_lo][cc + 1] = f2tf32(p1);
                Ps[prow_hi][cc]     = f2tf32(p2);
                Ps[prow_hi][cc + 1] = f2tf32(p3);
                of[nf][0] *= cr0; of[nf][1] *= cr0;
                of[nf][2] *= cr1; of[nf][3] *= cr1;
            }
            s0 += __shfl_xor_sync(0xffffffffu, s0, 1);
            s0 += __shfl_xor_sync(0xffffffffu, s0, 2);
            s1 += __shfl_xor_sync(0xffffffffu, s1, 1);
            s1 += __shfl_xor_sync(0xffffffffu, s1, 2);
            l0 = l0 * cr0 + s0;
            l1 = l1 * cr1 + s1;
            m0 = mn0; m1 = mn1;
            __syncwarp();

            #pragma unroll
            for (int k0 = 0; k0 < 8; k0++) {
                const int kb8 = k0 * 8;
                uint32_t a0, a1, a2, a3;
                ldm4(a0, a1, a2, a3, pbase + (uint32_t)kb8 * 4);
                #pragma unroll
                for (int p = 0; p < 4; p++) {
                    uint32_t b00, b01, b10, b11;
                    ldm4(b00, b01, b10, b11,
                         vbase + (uint32_t)(p * 16 * 68 + kb8) * 4);
                    mma_tf32(of[2*p][0], of[2*p][1], of[2*p][2], of[2*p][3],
                             a0, a1, a2, a3, b00, b01);
                    mma_tf32(of[2*p+1][0], of[2*p+1][1], of[2*p+1][2], of[2*p+1][3],
                             a0, a1, a2, a3, b10, b11);
                }
            }
        }
        __syncthreads();
    }

    // write output rows as fp16 (feeds fp16 proj GEMM)
    const float il0 = 1.0f / l0, il1 = 1.0f / l1;
    const int rowg_lo = b * T_ + qt_own * 64 + rlo;
    const int rowg_hi = rowg_lo + 8;
    #pragma unroll
    for (int nf = 0; nf < 8; nf++) {
        const int col = h * HD_ + nf * 8 + 2 * tig;
        *(__half2*)(g_yh + (size_t)rowg_lo * C_ + col) =
            __floats2half2_rn(of[nf][0] * il0, of[nf][1] * il0);
        *(__half2*)(g_yh + (size_t)rowg_hi * C_ + col) =
            __floats2half2_rn(of[nf][2] * il1, of[nf][3] * il1);
    }
}

// ---------------- launch ----------------
extern "C" void kernel_launch(void* const* d_in, const int* in_sizes, int n_in,
                              void* d_out, int out_size)
{
    const float* x      = (const float*)d_in[0];
    const float* qkv_w  = (const float*)d_in[1];
    const float* proj_w = (const float*)d_in[2];
    const float* proj_b = (const float*)d_in[3];
    const float* curv   = (const float*)d_in[4];
    float* out = (float*)d_out;

    void *pyh = nullptr, *pxh = nullptr, *pwqh = nullptr, *pwph = nullptr;
    cudaGetSymbolAddress(&pyh, g_yh);
    cudaGetSymbolAddress(&pxh, g_xh);
    cudaGetSymbolAddress(&pwqh, g_wqh);
    cudaGetSymbolAddress(&pwph, g_wph);

    cudaFuncSetAttribute(flash_tc,
                         cudaFuncAttributeMaxDynamicSharedMemorySize, FSM_BYTES);
    cudaFuncSetAttribute(mma_gemm<1>,
                         cudaFuncAttributeMaxDynamicSharedMemorySize, GSM_BYTES);
    cudaFuncSetAttribute(mma_gemm<2>,
                         cudaFuncAttributeMaxDynamicSharedMemorySize, GSM_BYTES);

    // 0) fp16 conversions + rotary table
    cvt_f16_kernel<<<(M_ * C_ / 4 + 255) / 256, 256>>>(
        (const float4*)x, (__half2*)pxh, M_ * C_ / 4);
    cvt_f16_kernel<<<(3 * C_ * C_ / 4 + 255) / 256, 256>>>(
        (const float4*)qkv_w, (__half2*)pwqh, 3 * C_ * C_ / 4);
    cvt_f16_kernel<<<(C_ * C_ / 4 + 255) / 256, 256>>>(
        (const float4*)proj_w, (__half2*)pwph, C_ * C_ / 4);
    rotab_kernel<<<T_ / 8, 256>>>();

    // 1) qkv GEMM (fp16) with fused rotary/norm/tq-tk/V-transpose epilogue
    mma_gemm<2><<<dim3(3 * C_ / 128, M_ / 128), 256, GSM_BYTES>>>(
        (const __half*)pxh, (const __half*)pwqh, nullptr, nullptr, M_, 3 * C_, C_, curv);

    // 2) flash: 2 q-tiles per block, shared K/V (tf32)
    flash_tc<<<dim3(T_ / 128, B_ * H_), 256, FSM_BYTES>>>(curv);

    // 3) out = y @ proj_w^T + proj_b (fp16 GEMM, fp32 out)
    mma_gemm<1><<<dim3(C_ / 128, M_ / 128), 256, GSM_BYTES>>>(
        (const __half*)pyh, (const __half*)pwph, proj_b, out, M_, C_, C_, nullptr);
}